// round 12
// baseline (speedup 1.0000x reference)
#include <cuda_runtime.h>
#include <cuda_fp16.h>
#include <cstdint>

// ---------------------------------------------------------------------------
// LSTM cell w/ diagonal peepholes, 2 launches:
//   1) convert: x|hx -> g_A fp16, W_ih|W_hh -> g_W fp16 (concat K=2048)
//   2) fused GEMM+epilogue: 512-thread CTA per 128(batch) x 128(gate-col)
//      tile (4 gate strips of 32 h). Warp grid 4x4, warp tile 32x32.
//      f16-accumulate HMMA, chain-4 (K=64) fp32 flush.
//      BKH=128, 2-stage pipeline (16 big kt iterations, 2 barriers each).
// 1 CTA/SM (139KB smem), 16 warps = 4/SMSP. 1024 CTAs = 6.92 waves.
// tcgen05 unavailable (harness PTX targets plain sm_103, no 'a' features).
// ---------------------------------------------------------------------------

#define MB 4096
#define HD 1024
#define KT 2048

#define BM 128              // batch rows per CTA
#define BKH 128             // K-halves per stage
#define NKT (KT / BKH)      // 16 outer iterations
#define RSB 272             // smem row stride bytes (256B data + 16 pad)
#define A_BYTES (BM * RSB)             // 34816
#define STG_BYTES (2 * A_BYTES)        // 69632 (A then B, both 128 rows)
#define SMEM_BYTES (2 * STG_BYTES)     // 139264 -> 1 CTA/SM

#define NTHR 512

// epilogue smem overlay — BYTE offsets (reuses pipeline buffers after mainloop)
#define EPS          132                        // fp32 acc row stride in floats
#define EPB_BS       (BM * EPS * 4)             // 67584: 128 floats (bias sums)
#define EPB_PI       (EPB_BS + 512)             // 68096: 32 floats
#define EPB_PF       (EPB_PI + 128)             // 68224: 32 floats (end 68352)

__device__ __half g_A[(size_t)MB * KT];
__device__ __half g_W[(size_t)4096 * KT];

// ----------------------------- helpers ------------------------------------
__device__ __forceinline__ uint32_t smem_u32(const void* p) {
    uint32_t a;
    asm("{ .reg .u64 t; cvta.to.shared.u64 t, %1; cvt.u32.u64 %0, t; }"
        : "=r"(a) : "l"(p));
    return a;
}
__device__ __forceinline__ void cp16(uint32_t dst, const void* src) {
    asm volatile("cp.async.cg.shared.global [%0], [%1], 16;"
                 :: "r"(dst), "l"(src) : "memory");
}
#define CP_COMMIT() asm volatile("cp.async.commit_group;" ::: "memory")
#define CP_WAIT1()  asm volatile("cp.async.wait_group 1;"  ::: "memory")

#define LDSM_X4(r0, r1, r2, r3, addr) \
    asm volatile("ldmatrix.sync.aligned.m8n8.x4.shared.b16 {%0,%1,%2,%3}, [%4];" \
                 : "=r"(r0), "=r"(r1), "=r"(r2), "=r"(r3) : "r"(addr))

// f16-accumulate HMMA
#define MMA16816H(c, a, b) \
    asm volatile("mma.sync.aligned.m16n8k16.row.col.f16.f16.f16.f16 " \
                 "{%0,%1}, {%2,%3,%4,%5}, {%6,%7}, {%0,%1};" \
                 : "+r"((c)[0]), "+r"((c)[1]) \
                 : "r"((a)[0]), "r"((a)[1]), "r"((a)[2]), "r"((a)[3]), \
                   "r"((b)[0]), "r"((b)[1]))

__device__ __forceinline__ float sigmoidf_(float v) {
    return 1.0f / (1.0f + expf(-v));
}

// ----------------------------- convert ------------------------------------
// Each thread converts 16 consecutive fp32 (4 float4, MLP=4) to fp16.
__global__ __launch_bounds__(256)
void convert_f16(const float* __restrict__ x,  const float* __restrict__ hx,
                 const float* __restrict__ wih, const float* __restrict__ whh) {
    const size_t NA16 = (size_t)MB * KT / 16;
    const size_t id = (size_t)blockIdx.x * blockDim.x + threadIdx.x;
    const size_t j   = (id < NA16) ? id : id - NA16;
    const size_t row = j >> 7;
    const size_t k16 = (j & 127) * 16;
    const float* src;
    __half* dst;
    if (id < NA16) {
        src = (k16 < HD) ? (x + row * HD + k16) : (hx + row * HD + (k16 - HD));
        dst = g_A + j * 16;
    } else {
        src = (k16 < HD) ? (wih + row * HD + k16) : (whh + row * HD + (k16 - HD));
        dst = g_W + j * 16;
    }
    float4 v0 = *(const float4*)(src);
    float4 v1 = *(const float4*)(src + 4);
    float4 v2 = *(const float4*)(src + 8);
    float4 v3 = *(const float4*)(src + 12);
    __half2 h_[8];
    h_[0] = __floats2half2_rn(v0.x, v0.y); h_[1] = __floats2half2_rn(v0.z, v0.w);
    h_[2] = __floats2half2_rn(v1.x, v1.y); h_[3] = __floats2half2_rn(v1.z, v1.w);
    h_[4] = __floats2half2_rn(v2.x, v2.y); h_[5] = __floats2half2_rn(v2.z, v2.w);
    h_[6] = __floats2half2_rn(v3.x, v3.y); h_[7] = __floats2half2_rn(v3.z, v3.w);
    *(uint4*)(dst)     = *(uint4*)&h_[0];
    *(uint4*)(dst + 8) = *(uint4*)&h_[4];
}

// ------------------------ fused GEMM + LSTM epilogue -----------------------
__global__ __launch_bounds__(NTHR, 1)
void lstm_gemm_fused(const float* __restrict__ cx,
                     const float* __restrict__ b_ih,
                     const float* __restrict__ b_hh,
                     const float* __restrict__ wpi,
                     const float* __restrict__ wpf,
                     float* __restrict__ out) {
    extern __shared__ char smem[];
    const uint32_t sb = smem_u32(smem);

    const int tid  = threadIdx.x;
    const int lane = tid & 31;
    const int warp = tid >> 5;           // 0..15
    const int wm   = warp >> 2;          // 0..3 (32 rows each)
    const int wn   = warp & 3;           // 0..3 (32 cols each = one gate)
    const int bm   = blockIdx.y * BM;    // batch block (128 rows)
    const int h0   = blockIdx.x * 32;    // 32 h-values per CTA

    // fill mapping: per stage A = 2048 chunks (128r x 16c), B = 2048.
    // 512 threads -> 4 A + 4 B chunks each (i adds 32 rows).
    const int r0c = tid >> 4;            // 0..31
    const int cc  = tid & 15;            // 0..15 (16B chunks across 256B row)
    const __half* pa0 = g_A + (size_t)(bm + r0c) * KT + cc * 8;
    const __half* pw0 = g_W + (size_t)(h0 + r0c) * KT + cc * 8;  // +32r = +1 strip
    const uint32_t so0 = (uint32_t)r0c * RSB + (uint32_t)cc * 16;

    const uint32_t aoff = (uint32_t)(lane & 15) * RSB + (uint32_t)(lane >> 4) * 16;
    const uint32_t boff = (uint32_t)(lane & 7) * RSB + (uint32_t)((lane >> 3) & 1) * 16
                        + (uint32_t)(lane >> 4) * (8 * RSB);

#define FILL(s_, ktoff_) do {                                                  \
        const uint32_t sa_ = sb + (uint32_t)(s_) * STG_BYTES;                  \
        const __half* pa_ = pa0 + (size_t)(ktoff_) * BKH;                      \
        const __half* pw_ = pw0 + (size_t)(ktoff_) * BKH;                      \
        _Pragma("unroll")                                                      \
        for (int i_ = 0; i_ < 4; i_++) {                                       \
            cp16(sa_ + so0 + i_ * (32 * RSB), pa_ + (size_t)i_ * (32 * KT));   \
            cp16(sa_ + A_BYTES + so0 + i_ * (32 * RSB),                        \
                 pw_ + (size_t)i_ * (1024 * KT));                              \
        }                                                                      \
    } while (0)

    FILL(0, 0); CP_COMMIT();
    FILL(1, 1); CP_COMMIT();

    float acc[2][4][4];                  // fp32 master (warp tile 32x32)
    #pragma unroll
    for (int i = 0; i < 2; i++)
        #pragma unroll
        for (int j = 0; j < 4; j++)
            #pragma unroll
            for (int e = 0; e < 4; e++) acc[i][j][e] = 0.0f;

    uint32_t hc[2][4][2];                // f16x2 short-chain accumulators
    uint32_t a[2][4], b[4][2];

    #pragma unroll 1
    for (int kt = 0; kt < NKT; kt++) {            // 16 iterations
        const int s = kt & 1;
        CP_WAIT1();
        __syncthreads();                          // stage s ready, prev fill done

        const uint32_t sa = sb + (uint32_t)s * STG_BYTES;
        const uint32_t sw = sa + A_BYTES;
        const uint32_t ab = sa + (uint32_t)(wm * 32) * RSB + aoff;
        const uint32_t bb = sw + (uint32_t)(wn * 32) * RSB + boff;

        #pragma unroll
        for (int ks = 0; ks < 8; ks++) {          // K=16 each
            if ((ks & 3) == 0) {                  // chain restart (K=64 chains)
                #pragma unroll
                for (int mt = 0; mt < 2; mt++)
                    #pragma unroll
                    for (int nt = 0; nt < 4; nt++) {
                        hc[mt][nt][0] = 0u; hc[mt][nt][1] = 0u;
                    }
            }
            #pragma unroll
            for (int mt = 0; mt < 2; mt++)
                LDSM_X4(a[mt][0], a[mt][1], a[mt][2], a[mt][3],
                        ab + (uint32_t)(mt * 16) * RSB + (uint32_t)ks * 32);
            #pragma unroll
            for (int np = 0; np < 2; np++)
                LDSM_X4(b[np * 2][0], b[np * 2][1],
                        b[np * 2 + 1][0], b[np * 2 + 1][1],
                        bb + (uint32_t)(np * 16) * RSB + (uint32_t)ks * 32);
            #pragma unroll
            for (int mt = 0; mt < 2; mt++)
                #pragma unroll
                for (int nt = 0; nt < 4; nt++)
                    MMA16816H(hc[mt][nt], a[mt], b[nt]);
            if ((ks & 3) == 3) {                  // flush chain into fp32
                #pragma unroll
                for (int mt = 0; mt < 2; mt++)
                    #pragma unroll
                    for (int nt = 0; nt < 4; nt++) {
                        const float2 f0 =
                            __half22float2(*(const __half2*)&hc[mt][nt][0]);
                        const float2 f1 =
                            __half22float2(*(const __half2*)&hc[mt][nt][1]);
                        acc[mt][nt][0] += f0.x; acc[mt][nt][1] += f0.y;
                        acc[mt][nt][2] += f1.x; acc[mt][nt][3] += f1.y;
                    }
            }
        }

        __syncthreads();                          // stage s fully consumed
        if (kt + 2 < NKT) FILL(s, kt + 2);
        CP_COMMIT();
    }
#undef FILL

    // ------------------ epilogue: stage accs through smem ------------------
    float* GA = (float*)(smem);            // [128][EPS] fp32 accs
    float* BS = (float*)(smem + EPB_BS);   // 128 floats: b_ih+b_hh per gate col
    float* PI = (float*)(smem + EPB_PI);   // 32 floats: diag(W_peephole_i)
    float* PF = (float*)(smem + EPB_PF);   // 32 floats: diag(W_peephole_f)

    const int g2 = lane >> 2;
    const int tc = lane & 3;
    #pragma unroll
    for (int mt = 0; mt < 2; mt++) {
        #pragma unroll
        for (int nt = 0; nt < 4; nt++) {
            const int row = wm * 32 + mt * 16 + g2;
            const int col = wn * 32 + nt * 8 + tc * 2;
            *(float2*)(GA + (size_t)row * EPS + col) =
                make_float2(acc[mt][nt][0], acc[mt][nt][1]);
            *(float2*)(GA + (size_t)(row + 8) * EPS + col) =
                make_float2(acc[mt][nt][2], acc[mt][nt][3]);
        }
    }
    if (tid < 128) {
        const int gcol = ((tid >> 5) << 10) + h0 + (tid & 31);
        BS[tid] = b_ih[gcol] + b_hh[gcol];
    } else if (tid < 160) {
        const int j = tid - 128;
        PI[j] = wpi[(size_t)(h0 + j) * (HD + 1)];
        PF[j] = wpf[(size_t)(h0 + j) * (HD + 1)];
    }
    __syncthreads();

    // each thread: 8 (b,h) pairs; lane == j (h index), coalesced I/O
    #pragma unroll 4
    for (int q = 0; q < 8; q++) {
        const int p = q * NTHR + tid;
        const int r = p >> 5;              // batch row within tile (0..127)
        const int j = p & 31;              // h within 32
        const float* gr = GA + (size_t)r * EPS;
        const float ig = gr[j]      + BS[j];
        const float fg = gr[32 + j] + BS[32 + j];
        const float gg = gr[64 + j] + BS[64 + j];
        const float og = gr[96 + j] + BS[96 + j];
        const float c  = cx[(size_t)(bm + r) * HD + h0 + j];
        const float i_s = sigmoidf_(ig + c * PI[j]);
        const float f_s = sigmoidf_(fg + c * PF[j]);
        const float g_t = tanhf(gg);
        const float cy  = f_s * c + i_s * g_t;
        const float o_s = sigmoidf_(og + cy * PF[j]);   // ref reuses W_f
        const float hy  = o_s * tanhf(cy);
        out[(size_t)(bm + r) * HD + h0 + j] = hy;
        out[(size_t)MB * HD + (size_t)(bm + r) * HD + h0 + j] = cy;
    }
}

// ---------------------------------------------------------------------------
extern "C" void kernel_launch(void* const* d_in, const int* in_sizes, int n_in,
                              void* d_out, int out_size) {
    const float* x    = (const float*)d_in[0];
    const float* hx   = (const float*)d_in[1];
    const float* cx   = (const float*)d_in[2];
    const float* w_ih = (const float*)d_in[3];
    const float* w_hh = (const float*)d_in[4];
    const float* b_ih = (const float*)d_in[5];
    const float* b_hh = (const float*)d_in[6];
    const float* wpi  = (const float*)d_in[7];
    const float* wpf  = (const float*)d_in[8];
    // d_in[9] (W_peephole_o) unused: reference reuses W_peephole_f.
    float* out = (float*)d_out;

    convert_f16<<<4096, 256>>>(x, hx, w_ih, w_hh);

    static int smem_set = 0;
    if (!smem_set) {
        cudaFuncSetAttribute(lstm_gemm_fused,
                             cudaFuncAttributeMaxDynamicSharedMemorySize,
                             SMEM_BYTES);
        smem_set = 1;
    }
    dim3 grid(32, 32);   // 32 h-blocks x 32 batch-blocks = 1024 CTAs
    lstm_gemm_fused<<<grid, NTHR, SMEM_BYTES>>>(cx, b_ih, b_hh, wpi, wpf, out);
}

// round 13
// speedup vs baseline: 1.2587x; 1.2587x over previous
#include <cuda_runtime.h>
#include <cuda_fp16.h>
#include <cstdint>

// ---------------------------------------------------------------------------
// LSTM cell w/ diagonal peepholes (round-4 champion structure):
//   1) convert: x|hx -> g_A fp16 [4096x2048], W_ih|W_hh -> g_W fp16 [4096x2048]
//   2) GEMM: g_gates(fp16) = A @ W^T  (mma.sync m16n8k16 f32-acc,
//      3-stage cp.async pipeline, BK=64, ldmatrix.x4 both operands, 2 CTA/SM)
//   3) vectorized elementwise LSTM epilogue (8 elems/thread)
// tcgen05 unavailable (harness PTX targets plain sm_103, no 'a' features).
// ---------------------------------------------------------------------------

#define MB 4096
#define HD 1024
#define NG 4096
#define KT 2048

#define BM 128
#define BN 128
#define BKH 64              // K-halves per stage
#define NSTG 3
#define RSB 144             // smem row stride bytes (128B data + 16 pad)
#define TILE_BYTES (BM * RSB)          // 18432
#define STG_BYTES  (2 * TILE_BYTES)    // 36864 (A then B)
#define SMEM_BYTES (NSTG * STG_BYTES)  // 110592

__device__ __half g_A[(size_t)MB * KT];
__device__ __half g_W[(size_t)NG * KT];
__device__ __half g_gates[(size_t)MB * NG];     // fp16 pre-activation gates

// ----------------------------- helpers ------------------------------------
__device__ __forceinline__ uint32_t smem_u32(const void* p) {
    uint32_t a;
    asm("{ .reg .u64 t; cvta.to.shared.u64 t, %1; cvt.u32.u64 %0, t; }"
        : "=r"(a) : "l"(p));
    return a;
}
__device__ __forceinline__ void cp16(uint32_t dst, const void* src) {
    asm volatile("cp.async.cg.shared.global [%0], [%1], 16;"
                 :: "r"(dst), "l"(src) : "memory");
}
#define CP_COMMIT() asm volatile("cp.async.commit_group;" ::: "memory")
#define CP_WAIT1()  asm volatile("cp.async.wait_group 1;"  ::: "memory")

#define LDSM_X4(r0, r1, r2, r3, addr) \
    asm volatile("ldmatrix.sync.aligned.m8n8.x4.shared.b16 {%0,%1,%2,%3}, [%4];" \
                 : "=r"(r0), "=r"(r1), "=r"(r2), "=r"(r3) : "r"(addr))

#define MMA16816(c, a, b) \
    asm volatile("mma.sync.aligned.m16n8k16.row.col.f32.f16.f16.f32 " \
                 "{%0,%1,%2,%3}, {%4,%5,%6,%7}, {%8,%9}, {%0,%1,%2,%3};" \
                 : "+f"((c)[0]), "+f"((c)[1]), "+f"((c)[2]), "+f"((c)[3]) \
                 : "r"((a)[0]), "r"((a)[1]), "r"((a)[2]), "r"((a)[3]), \
                   "r"((b)[0]), "r"((b)[1]))

__device__ __forceinline__ float sigmoidf_(float v) {
    return 1.0f / (1.0f + expf(-v));
}

// ----------------------------- convert ------------------------------------
// Each thread converts 32 consecutive fp32 (8 float4, MLP=8) to fp16.
__global__ __launch_bounds__(256)
void convert_f16(const float* __restrict__ x,  const float* __restrict__ hx,
                 const float* __restrict__ wih, const float* __restrict__ whh) {
    const size_t NA32 = (size_t)MB * KT / 32;   // 256K picks for A, 256K for W
    const size_t id = (size_t)blockIdx.x * blockDim.x + threadIdx.x;
    const size_t j   = (id < NA32) ? id : id - NA32;
    const size_t row = j >> 6;                  // 64 32-elem picks per row
    const size_t k32 = (j & 63) * 32;
    const float* src;
    __half* dst;
    if (id < NA32) {
        src = (k32 < HD) ? (x + row * HD + k32) : (hx + row * HD + (k32 - HD));
        dst = g_A + j * 32;
    } else {
        src = (k32 < HD) ? (wih + row * HD + k32) : (whh + row * HD + (k32 - HD));
        dst = g_W + j * 32;
    }
    float4 v[8];
    #pragma unroll
    for (int i = 0; i < 8; i++) v[i] = *(const float4*)(src + i * 4);
    __half2 h_[16];
    #pragma unroll
    for (int i = 0; i < 8; i++) {
        h_[i * 2]     = __floats2half2_rn(v[i].x, v[i].y);
        h_[i * 2 + 1] = __floats2half2_rn(v[i].z, v[i].w);
    }
    #pragma unroll
    for (int i = 0; i < 4; i++)
        *(uint4*)(dst + i * 8) = *(uint4*)&h_[i * 4];
}

// ----------------------------- GEMM (round-4 champion) ---------------------
__global__ __launch_bounds__(256, 2)
void gates_gemm_f16() {
    extern __shared__ char smem[];
    const uint32_t sb = smem_u32(smem);

    const int tid  = threadIdx.x;
    const int lane = tid & 31;
    const int warp = tid >> 5;
    const int wm   = warp >> 2;          // 0..1 (64 rows each)
    const int wn   = warp & 3;           // 0..3 (32 cols each)
    const int bm   = blockIdx.y * BM;
    const int bn   = blockIdx.x * BN;

    const uint32_t aoff = (uint32_t)(lane & 15) * RSB + (uint32_t)(lane >> 4) * 16;
    const uint32_t boff = (uint32_t)(lane & 7) * RSB + (uint32_t)((lane >> 3) & 1) * 16
                        + (uint32_t)(lane >> 4) * (8 * RSB);

#define FILL(s_, kt_) do {                                                       \
        const uint32_t sa_ = sb + (uint32_t)(s_) * STG_BYTES;                    \
        const __half* ga_ = g_A + (size_t)(bm) * KT + (size_t)(kt_) * BKH;       \
        const __half* gw_ = g_W + (size_t)(bn) * KT + (size_t)(kt_) * BKH;       \
        _Pragma("unroll")                                                        \
        for (int i_ = 0; i_ < 4; i_++) {                                         \
            const int f_ = tid + i_ * 256;                                       \
            const int r_ = f_ >> 3, c_ = f_ & 7;                                 \
            cp16(sa_ + (uint32_t)r_ * RSB + (uint32_t)c_ * 16,                   \
                 ga_ + (size_t)r_ * KT + c_ * 8);                                \
            cp16(sa_ + TILE_BYTES + (uint32_t)r_ * RSB + (uint32_t)c_ * 16,      \
                 gw_ + (size_t)r_ * KT + c_ * 8);                                \
        }                                                                        \
    } while (0)

    FILL(0, 0); CP_COMMIT();
    FILL(1, 1); CP_COMMIT();

    float acc[4][4][4];
    #pragma unroll
    for (int i = 0; i < 4; i++)
        #pragma unroll
        for (int j = 0; j < 4; j++)
            #pragma unroll
            for (int e = 0; e < 4; e++) acc[i][j][e] = 0.0f;

    #pragma unroll 1
    for (int kt = 0; kt < KT / BKH; kt++) {       // 32 stages
        const int s = kt % 3;
        CP_WAIT1();
        __syncthreads();
        if (kt + 2 < KT / BKH) FILL((kt + 2) % 3, kt + 2);
        CP_COMMIT();

        const uint32_t sa = sb + (uint32_t)s * STG_BYTES;
        const uint32_t sw = sa + TILE_BYTES;
        #pragma unroll
        for (int ks = 0; ks < 4; ks++) {          // 16 halves each
            uint32_t a[4][4], b[4][2];
            #pragma unroll
            for (int mt = 0; mt < 4; mt++) {
                const uint32_t ad = sa + (uint32_t)(wm * 64 + mt * 16) * RSB
                                       + (uint32_t)ks * 32 + aoff;
                LDSM_X4(a[mt][0], a[mt][1], a[mt][2], a[mt][3], ad);
            }
            #pragma unroll
            for (int np = 0; np < 2; np++) {      // nt pairs {0,1},{2,3}
                const uint32_t bd = sw + (uint32_t)(wn * 32 + np * 16) * RSB
                                       + (uint32_t)ks * 32 + boff;
                LDSM_X4(b[np * 2][0], b[np * 2][1],
                        b[np * 2 + 1][0], b[np * 2 + 1][1], bd);
            }
            #pragma unroll
            for (int mt = 0; mt < 4; mt++)
                #pragma unroll
                for (int nt = 0; nt < 4; nt++)
                    MMA16816(acc[mt][nt], a[mt], b[nt]);
        }
    }
#undef FILL

    // store acc -> g_gates (fp16)
    const int g  = lane >> 2;
    const int tc = lane & 3;
    #pragma unroll
    for (int mt = 0; mt < 4; mt++) {
        #pragma unroll
        for (int nt = 0; nt < 4; nt++) {
            const int row = bm + wm * 64 + mt * 16 + g;
            const int col = bn + wn * 32 + nt * 8 + tc * 2;
            __half2* p0 = (__half2*)(g_gates + (size_t)row * NG + col);
            *p0 = __floats2half2_rn(acc[mt][nt][0], acc[mt][nt][1]);
            __half2* p1 = (__half2*)(g_gates + (size_t)(row + 8) * NG + col);
            *p1 = __floats2half2_rn(acc[mt][nt][2], acc[mt][nt][3]);
        }
    }
}

// ----------------------------- LSTM epilogue (8 elems/thread) --------------
__global__ __launch_bounds__(256)
void lstm_epilogue(const float* __restrict__ cx,
                   const float* __restrict__ b_ih,
                   const float* __restrict__ b_hh,
                   const float* __restrict__ wpi,
                   const float* __restrict__ wpf,
                   float* __restrict__ out) {
    const int idx8 = (blockIdx.x * 256 + threadIdx.x) * 8;  // 8 elems/thread
    const int b = idx8 >> 10;
    const int h = idx8 & (HD - 1);

    const __half* gr = g_gates + (size_t)b * NG;
    float gv[4][8];
    #pragma unroll
    for (int G = 0; G < 4; G++) {
        const uint4 raw = *(const uint4*)(gr + G * HD + h);
        const float2 f0 = __half22float2(*(const __half2*)&raw.x);
        const float2 f1 = __half22float2(*(const __half2*)&raw.y);
        const float2 f2 = __half22float2(*(const __half2*)&raw.z);
        const float2 f3 = __half22float2(*(const __half2*)&raw.w);
        gv[G][0] = f0.x; gv[G][1] = f0.y; gv[G][2] = f1.x; gv[G][3] = f1.y;
        gv[G][4] = f2.x; gv[G][5] = f2.y; gv[G][6] = f3.x; gv[G][7] = f3.y;
    }
    float bs[4][8];
    #pragma unroll
    for (int G = 0; G < 4; G++) {
        const float4 bi0 = *(const float4*)(b_ih + G * HD + h);
        const float4 bh0 = *(const float4*)(b_hh + G * HD + h);
        const float4 bi1 = *(const float4*)(b_ih + G * HD + h + 4);
        const float4 bh1 = *(const float4*)(b_hh + G * HD + h + 4);
        bs[G][0] = bi0.x + bh0.x; bs[G][1] = bi0.y + bh0.y;
        bs[G][2] = bi0.z + bh0.z; bs[G][3] = bi0.w + bh0.w;
        bs[G][4] = bi1.x + bh1.x; bs[G][5] = bi1.y + bh1.y;
        bs[G][6] = bi1.z + bh1.z; bs[G][7] = bi1.w + bh1.w;
    }
    const float4 c0 = *(const float4*)(cx + idx8);
    const float4 c1 = *(const float4*)(cx + idx8 + 4);
    const float cv[8] = {c0.x, c0.y, c0.z, c0.w, c1.x, c1.y, c1.z, c1.w};

    float hy[8], cyv[8];
    #pragma unroll
    for (int e = 0; e < 8; e++) {
        const float pi = wpi[(size_t)(h + e) * (HD + 1)];
        const float pf = wpf[(size_t)(h + e) * (HD + 1)];
        const float c  = cv[e];
        const float i_s = sigmoidf_(gv[0][e] + bs[0][e] + c * pi);
        const float f_s = sigmoidf_(gv[1][e] + bs[1][e] + c * pf);
        const float g_t = tanhf(gv[2][e] + bs[2][e]);
        const float cy  = f_s * c + i_s * g_t;
        const float o_s = sigmoidf_(gv[3][e] + bs[3][e] + cy * pf);  // ref reuses W_f
        hy[e]  = o_s * tanhf(cy);
        cyv[e] = cy;
    }
    *(float4*)(out + idx8)     = make_float4(hy[0], hy[1], hy[2], hy[3]);
    *(float4*)(out + idx8 + 4) = make_float4(hy[4], hy[5], hy[6], hy[7]);
    float* oc = out + (size_t)MB * HD + idx8;
    *(float4*)(oc)     = make_float4(cyv[0], cyv[1], cyv[2], cyv[3]);
    *(float4*)(oc + 4) = make_float4(cyv[4], cyv[5], cyv[6], cyv[7]);
}

// ---------------------------------------------------------------------------
extern "C" void kernel_launch(void* const* d_in, const int* in_sizes, int n_in,
                              void* d_out, int out_size) {
    const float* x    = (const float*)d_in[0];
    const float* hx   = (const float*)d_in[1];
    const float* cx   = (const float*)d_in[2];
    const float* w_ih = (const float*)d_in[3];
    const float* w_hh = (const float*)d_in[4];
    const float* b_ih = (const float*)d_in[5];
    const float* b_hh = (const float*)d_in[6];
    const float* wpi  = (const float*)d_in[7];
    const float* wpf  = (const float*)d_in[8];
    // d_in[9] (W_peephole_o) unused: reference reuses W_peephole_f.
    float* out = (float*)d_out;

    // 512K threads x 32 elems = 16M elems (A + W)
    convert_f16<<<2048, 256>>>(x, hx, w_ih, w_hh);

    static int smem_set = 0;
    if (!smem_set) {
        cudaFuncSetAttribute(gates_gemm_f16,
                             cudaFuncAttributeMaxDynamicSharedMemorySize,
                             SMEM_BYTES);
        smem_set = 1;
    }
    dim3 grid(NG / BN, MB / BM);   // 32 x 32
    gates_gemm_f16<<<grid, 256, SMEM_BYTES>>>();

    // 4.19M elems / 8 per thread / 256 per block = 2048 blocks
    lstm_epilogue<<<(MB * HD) / 2048, 256>>>(cx, b_ih, b_hh, wpi, wpf, out);
}

// round 14
// speedup vs baseline: 1.4084x; 1.1189x over previous
#include <cuda_runtime.h>
#include <cuda_fp16.h>
#include <cstdint>

// ---------------------------------------------------------------------------
// LSTM cell w/ diagonal peepholes (round-4 champion GEMM):
//   1) convert (16 elem/thread) + prep tail: extracts diag(W_pi), diag(W_pf),
//      bias sums into packed __device__ arrays for a coalesced epilogue.
//   2) GEMM: g_gates(fp16) = A @ W^T  (mma.sync m16n8k16 f32-acc,
//      3-stage cp.async pipeline, BK=64, ldmatrix.x4 both operands, 2 CTA/SM)
//      -- byte-identical to the measured-champion round-4 mainloop.
//   3) coalesced elementwise LSTM epilogue (4 elems/thread).
// tcgen05 unavailable (harness PTX targets plain sm_103, no 'a' features).
// ---------------------------------------------------------------------------

#define MB 4096
#define HD 1024
#define NG 4096
#define KT 2048

#define BM 128
#define BN 128
#define BKH 64              // K-halves per stage
#define NSTG 3
#define RSB 144             // smem row stride bytes (128B data + 16 pad)
#define TILE_BYTES (BM * RSB)          // 18432
#define STG_BYTES  (2 * TILE_BYTES)    // 36864 (A then B)
#define SMEM_BYTES (NSTG * STG_BYTES)  // 110592

__device__ __half g_A[(size_t)MB * KT];
__device__ __half g_W[(size_t)NG * KT];
__device__ __half g_gates[(size_t)MB * NG];     // fp16 pre-activation gates
__device__ float  g_BS[NG];                     // b_ih + b_hh (packed)
__device__ float  g_PI[HD];                     // diag(W_peephole_i)
__device__ float  g_PF[HD];                     // diag(W_peephole_f)

// ----------------------------- helpers ------------------------------------
__device__ __forceinline__ uint32_t smem_u32(const void* p) {
    uint32_t a;
    asm("{ .reg .u64 t; cvta.to.shared.u64 t, %1; cvt.u32.u64 %0, t; }"
        : "=r"(a) : "l"(p));
    return a;
}
__device__ __forceinline__ void cp16(uint32_t dst, const void* src) {
    asm volatile("cp.async.cg.shared.global [%0], [%1], 16;"
                 :: "r"(dst), "l"(src) : "memory");
}
#define CP_COMMIT() asm volatile("cp.async.commit_group;" ::: "memory")
#define CP_WAIT1()  asm volatile("cp.async.wait_group 1;"  ::: "memory")

#define LDSM_X4(r0, r1, r2, r3, addr) \
    asm volatile("ldmatrix.sync.aligned.m8n8.x4.shared.b16 {%0,%1,%2,%3}, [%4];" \
                 : "=r"(r0), "=r"(r1), "=r"(r2), "=r"(r3) : "r"(addr))

#define MMA16816(c, a, b) \
    asm volatile("mma.sync.aligned.m16n8k16.row.col.f32.f16.f16.f32 " \
                 "{%0,%1,%2,%3}, {%4,%5,%6,%7}, {%8,%9}, {%0,%1,%2,%3};" \
                 : "+f"((c)[0]), "+f"((c)[1]), "+f"((c)[2]), "+f"((c)[3]) \
                 : "r"((a)[0]), "r"((a)[1]), "r"((a)[2]), "r"((a)[3]), \
                   "r"((b)[0]), "r"((b)[1]))

__device__ __forceinline__ float sigmoidf_(float v) {
    return 1.0f / (1.0f + expf(-v));
}

// ----------------------------- convert + prep -----------------------------
// Data blocks (0..4095): each thread converts 16 consecutive fp32 to fp16.
// Prep blocks (4096..4119): extract bias sums + peephole diagonals.
__global__ __launch_bounds__(256)
void convert_f16(const float* __restrict__ x,  const float* __restrict__ hx,
                 const float* __restrict__ wih, const float* __restrict__ whh,
                 const float* __restrict__ b_ih, const float* __restrict__ b_hh,
                 const float* __restrict__ wpi, const float* __restrict__ wpf) {
    const size_t NA16 = (size_t)MB * KT / 16;   // 512K picks for A, 512K for W
    const size_t id = (size_t)blockIdx.x * blockDim.x + threadIdx.x;
    if (id < 2 * NA16) {
        const size_t j   = (id < NA16) ? id : id - NA16;
        const size_t row = j >> 7;
        const size_t k16 = (j & 127) * 16;
        const float* src;
        __half* dst;
        if (id < NA16) {
            src = (k16 < HD) ? (x + row * HD + k16) : (hx + row * HD + (k16 - HD));
            dst = g_A + j * 16;
        } else {
            src = (k16 < HD) ? (wih + row * HD + k16) : (whh + row * HD + (k16 - HD));
            dst = g_W + j * 16;
        }
        float4 v0 = *(const float4*)(src);
        float4 v1 = *(const float4*)(src + 4);
        float4 v2 = *(const float4*)(src + 8);
        float4 v3 = *(const float4*)(src + 12);
        __half2 h_[8];
        h_[0] = __floats2half2_rn(v0.x, v0.y); h_[1] = __floats2half2_rn(v0.z, v0.w);
        h_[2] = __floats2half2_rn(v1.x, v1.y); h_[3] = __floats2half2_rn(v1.z, v1.w);
        h_[4] = __floats2half2_rn(v2.x, v2.y); h_[5] = __floats2half2_rn(v2.z, v2.w);
        h_[6] = __floats2half2_rn(v3.x, v3.y); h_[7] = __floats2half2_rn(v3.z, v3.w);
        *(uint4*)(dst)     = *(uint4*)&h_[0];
        *(uint4*)(dst + 8) = *(uint4*)&h_[4];
    } else {
        const size_t p = id - 2 * NA16;          // 0 .. 6143
        if (p < NG) {
            g_BS[p] = b_ih[p] + b_hh[p];
        } else if (p < NG + HD) {
            const size_t h = p - NG;
            g_PI[h] = wpi[h * (HD + 1)];
        } else if (p < NG + 2 * HD) {
            const size_t h = p - NG - HD;
            g_PF[h] = wpf[h * (HD + 1)];
        }
    }
}

// ----------------------------- GEMM (round-4 champion) ---------------------
__global__ __launch_bounds__(256, 2)
void gates_gemm_f16() {
    extern __shared__ char smem[];
    const uint32_t sb = smem_u32(smem);

    const int tid  = threadIdx.x;
    const int lane = tid & 31;
    const int warp = tid >> 5;
    const int wm   = warp >> 2;          // 0..1 (64 rows each)
    const int wn   = warp & 3;           // 0..3 (32 cols each)
    const int bm   = blockIdx.y * BM;
    const int bn   = blockIdx.x * BN;

    const uint32_t aoff = (uint32_t)(lane & 15) * RSB + (uint32_t)(lane >> 4) * 16;
    const uint32_t boff = (uint32_t)(lane & 7) * RSB + (uint32_t)((lane >> 3) & 1) * 16
                        + (uint32_t)(lane >> 4) * (8 * RSB);

#define FILL(s_, kt_) do {                                                       \
        const uint32_t sa_ = sb + (uint32_t)(s_) * STG_BYTES;                    \
        const __half* ga_ = g_A + (size_t)(bm) * KT + (size_t)(kt_) * BKH;       \
        const __half* gw_ = g_W + (size_t)(bn) * KT + (size_t)(kt_) * BKH;       \
        _Pragma("unroll")                                                        \
        for (int i_ = 0; i_ < 4; i_++) {                                         \
            const int f_ = tid + i_ * 256;                                       \
            const int r_ = f_ >> 3, c_ = f_ & 7;                                 \
            cp16(sa_ + (uint32_t)r_ * RSB + (uint32_t)c_ * 16,                   \
                 ga_ + (size_t)r_ * KT + c_ * 8);                                \
            cp16(sa_ + TILE_BYTES + (uint32_t)r_ * RSB + (uint32_t)c_ * 16,      \
                 gw_ + (size_t)r_ * KT + c_ * 8);                                \
        }                                                                        \
    } while (0)

    FILL(0, 0); CP_COMMIT();
    FILL(1, 1); CP_COMMIT();

    float acc[4][4][4];
    #pragma unroll
    for (int i = 0; i < 4; i++)
        #pragma unroll
        for (int j = 0; j < 4; j++)
            #pragma unroll
            for (int e = 0; e < 4; e++) acc[i][j][e] = 0.0f;

    #pragma unroll 1
    for (int kt = 0; kt < KT / BKH; kt++) {       // 32 stages
        const int s = kt % 3;
        CP_WAIT1();
        __syncthreads();
        if (kt + 2 < KT / BKH) FILL((kt + 2) % 3, kt + 2);
        CP_COMMIT();

        const uint32_t sa = sb + (uint32_t)s * STG_BYTES;
        const uint32_t sw = sa + TILE_BYTES;
        #pragma unroll
        for (int ks = 0; ks < 4; ks++) {          // 16 halves each
            uint32_t a[4][4], b[4][2];
            #pragma unroll
            for (int mt = 0; mt < 4; mt++) {
                const uint32_t ad = sa + (uint32_t)(wm * 64 + mt * 16) * RSB
                                       + (uint32_t)ks * 32 + aoff;
                LDSM_X4(a[mt][0], a[mt][1], a[mt][2], a[mt][3], ad);
            }
            #pragma unroll
            for (int np = 0; np < 2; np++) {      // nt pairs {0,1},{2,3}
                const uint32_t bd = sw + (uint32_t)(wn * 32 + np * 16) * RSB
                                       + (uint32_t)ks * 32 + boff;
                LDSM_X4(b[np * 2][0], b[np * 2][1],
                        b[np * 2 + 1][0], b[np * 2 + 1][1], bd);
            }
            #pragma unroll
            for (int mt = 0; mt < 4; mt++)
                #pragma unroll
                for (int nt = 0; nt < 4; nt++)
                    MMA16816(acc[mt][nt], a[mt], b[nt]);
        }
    }
#undef FILL

    // store acc -> g_gates (fp16)
    const int g  = lane >> 2;
    const int tc = lane & 3;
    #pragma unroll
    for (int mt = 0; mt < 4; mt++) {
        #pragma unroll
        for (int nt = 0; nt < 4; nt++) {
            const int row = bm + wm * 64 + mt * 16 + g;
            const int col = bn + wn * 32 + nt * 8 + tc * 2;
            __half2* p0 = (__half2*)(g_gates + (size_t)row * NG + col);
            *p0 = __floats2half2_rn(acc[mt][nt][0], acc[mt][nt][1]);
            __half2* p1 = (__half2*)(g_gates + (size_t)(row + 8) * NG + col);
            *p1 = __floats2half2_rn(acc[mt][nt][2], acc[mt][nt][3]);
        }
    }
}

// ----------------------------- LSTM epilogue (coalesced) -------------------
__global__ __launch_bounds__(256)
void lstm_epilogue(const float* __restrict__ cx, float* __restrict__ out) {
    const int idx4 = (blockIdx.x * 256 + threadIdx.x) * 4;  // 4 elems/thread
    const int b = idx4 >> 10;
    const int h = idx4 & (HD - 1);

    const __half* gr = g_gates + (size_t)b * NG;
    float ig[4], fg[4], gg[4], og[4];
    #pragma unroll
    for (int G = 0; G < 4; G++) {
        const uint2 raw = *(const uint2*)(gr + G * HD + h);
        const float2 lo = __half22float2(*(const __half2*)&raw.x);
        const float2 hi = __half22float2(*(const __half2*)&raw.y);
        float* dst = (G == 0) ? ig : (G == 1) ? fg : (G == 2) ? gg : og;
        dst[0] = lo.x; dst[1] = lo.y; dst[2] = hi.x; dst[3] = hi.y;
    }
    const float4 bs0 = *(const float4*)(g_BS + h);
    const float4 bs1 = *(const float4*)(g_BS + HD + h);
    const float4 bs2 = *(const float4*)(g_BS + 2 * HD + h);
    const float4 bs3 = *(const float4*)(g_BS + 3 * HD + h);
    const float4 pi4 = *(const float4*)(g_PI + h);
    const float4 pf4 = *(const float4*)(g_PF + h);
    const float4 c4  = *(const float4*)(cx + idx4);

    const float bsi[4] = {bs0.x, bs0.y, bs0.z, bs0.w};
    const float bsf[4] = {bs1.x, bs1.y, bs1.z, bs1.w};
    const float bsg[4] = {bs2.x, bs2.y, bs2.z, bs2.w};
    const float bso[4] = {bs3.x, bs3.y, bs3.z, bs3.w};
    const float piv[4] = {pi4.x, pi4.y, pi4.z, pi4.w};
    const float pfv[4] = {pf4.x, pf4.y, pf4.z, pf4.w};
    const float cv[4]  = {c4.x, c4.y, c4.z, c4.w};

    float hy[4], cy[4];
    #pragma unroll
    for (int e = 0; e < 4; e++) {
        const float c  = cv[e];
        const float i_s = sigmoidf_(ig[e] + bsi[e] + c * piv[e]);
        const float f_s = sigmoidf_(fg[e] + bsf[e] + c * pfv[e]);
        const float g_t = tanhf(gg[e] + bsg[e]);
        const float cyv = f_s * c + i_s * g_t;
        const float o_s = sigmoidf_(og[e] + bso[e] + cyv * pfv[e]);  // ref reuses W_f
        hy[e] = o_s * tanhf(cyv);
        cy[e] = cyv;
    }
    *(float4*)(out + idx4) = make_float4(hy[0], hy[1], hy[2], hy[3]);
    *(float4*)(out + (size_t)MB * HD + idx4) = make_float4(cy[0], cy[1], cy[2], cy[3]);
}

// ---------------------------------------------------------------------------
extern "C" void kernel_launch(void* const* d_in, const int* in_sizes, int n_in,
                              void* d_out, int out_size) {
    const float* x    = (const float*)d_in[0];
    const float* hx   = (const float*)d_in[1];
    const float* cx   = (const float*)d_in[2];
    const float* w_ih = (const float*)d_in[3];
    const float* w_hh = (const float*)d_in[4];
    const float* b_ih = (const float*)d_in[5];
    const float* b_hh = (const float*)d_in[6];
    const float* wpi  = (const float*)d_in[7];
    const float* wpf  = (const float*)d_in[8];
    // d_in[9] (W_peephole_o) unused: reference reuses W_peephole_f.
    float* out = (float*)d_out;

    // 4096 data blocks + 24 prep blocks (6144 prep elements)
    convert_f16<<<4120, 256>>>(x, hx, w_ih, w_hh, b_ih, b_hh, wpi, wpf);

    static int smem_set = 0;
    if (!smem_set) {
        cudaFuncSetAttribute(gates_gemm_f16,
                             cudaFuncAttributeMaxDynamicSharedMemorySize,
                             SMEM_BYTES);
        smem_set = 1;
    }
    dim3 grid(NG / BN, MB / BM);   // 32 x 32
    gates_gemm_f16<<<grid, 256, SMEM_BYTES>>>();

    lstm_epilogue<<<(MB * HD) / 1024, 256>>>(cx, out);
}

// round 15
// speedup vs baseline: 1.4191x; 1.0076x over previous
#include <cuda_runtime.h>
#include <cuda_fp16.h>
#include <cstdint>

// ---------------------------------------------------------------------------
// LSTM cell w/ diagonal peepholes (round-14 champion + epilogue row-pairing):
//   1) convert (16 elem/thread) + prep tail: extracts diag(W_pi), diag(W_pf),
//      bias sums into packed __device__ arrays for a coalesced epilogue.
//   2) GEMM: g_gates(fp16) = A @ W^T  (mma.sync m16n8k16 f32-acc,
//      3-stage cp.async pipeline, BK=64, ldmatrix.x4 both operands, 2 CTA/SM)
//      -- byte-identical to the measured-champion mainloop (~200us, pipe floor).
//   3) coalesced LSTM epilogue, 2 batch rows per thread (reuses h-constants).
// tcgen05 unavailable (harness PTX targets plain sm_103, no 'a' features).
// ---------------------------------------------------------------------------

#define MB 4096
#define HD 1024
#define NG 4096
#define KT 2048

#define BM 128
#define BN 128
#define BKH 64              // K-halves per stage
#define NSTG 3
#define RSB 144             // smem row stride bytes (128B data + 16 pad)
#define TILE_BYTES (BM * RSB)          // 18432
#define STG_BYTES  (2 * TILE_BYTES)    // 36864 (A then B)
#define SMEM_BYTES (NSTG * STG_BYTES)  // 110592

__device__ __half g_A[(size_t)MB * KT];
__device__ __half g_W[(size_t)NG * KT];
__device__ __half g_gates[(size_t)MB * NG];     // fp16 pre-activation gates
__device__ float  g_BS[NG];                     // b_ih + b_hh (packed)
__device__ float  g_PI[HD];                     // diag(W_peephole_i)
__device__ float  g_PF[HD];                     // diag(W_peephole_f)

// ----------------------------- helpers ------------------------------------
__device__ __forceinline__ uint32_t smem_u32(const void* p) {
    uint32_t a;
    asm("{ .reg .u64 t; cvta.to.shared.u64 t, %1; cvt.u32.u64 %0, t; }"
        : "=r"(a) : "l"(p));
    return a;
}
__device__ __forceinline__ void cp16(uint32_t dst, const void* src) {
    asm volatile("cp.async.cg.shared.global [%0], [%1], 16;"
                 :: "r"(dst), "l"(src) : "memory");
}
#define CP_COMMIT() asm volatile("cp.async.commit_group;" ::: "memory")
#define CP_WAIT1()  asm volatile("cp.async.wait_group 1;"  ::: "memory")

#define LDSM_X4(r0, r1, r2, r3, addr) \
    asm volatile("ldmatrix.sync.aligned.m8n8.x4.shared.b16 {%0,%1,%2,%3}, [%4];" \
                 : "=r"(r0), "=r"(r1), "=r"(r2), "=r"(r3) : "r"(addr))

#define MMA16816(c, a, b) \
    asm volatile("mma.sync.aligned.m16n8k16.row.col.f32.f16.f16.f32 " \
                 "{%0,%1,%2,%3}, {%4,%5,%6,%7}, {%8,%9}, {%0,%1,%2,%3};" \
                 : "+f"((c)[0]), "+f"((c)[1]), "+f"((c)[2]), "+f"((c)[3]) \
                 : "r"((a)[0]), "r"((a)[1]), "r"((a)[2]), "r"((a)[3]), \
                   "r"((b)[0]), "r"((b)[1]))

__device__ __forceinline__ float sigmoidf_(float v) {
    return 1.0f / (1.0f + expf(-v));
}

// ----------------------------- convert + prep -----------------------------
// Data blocks (0..4095): each thread converts 16 consecutive fp32 to fp16.
// Prep blocks (4096..4119): extract bias sums + peephole diagonals.
__global__ __launch_bounds__(256)
void convert_f16(const float* __restrict__ x,  const float* __restrict__ hx,
                 const float* __restrict__ wih, const float* __restrict__ whh,
                 const float* __restrict__ b_ih, const float* __restrict__ b_hh,
                 const float* __restrict__ wpi, const float* __restrict__ wpf) {
    const size_t NA16 = (size_t)MB * KT / 16;   // 512K picks for A, 512K for W
    const size_t id = (size_t)blockIdx.x * blockDim.x + threadIdx.x;
    if (id < 2 * NA16) {
        const size_t j   = (id < NA16) ? id : id - NA16;
        const size_t row = j >> 7;
        const size_t k16 = (j & 127) * 16;
        const float* src;
        __half* dst;
        if (id < NA16) {
            src = (k16 < HD) ? (x + row * HD + k16) : (hx + row * HD + (k16 - HD));
            dst = g_A + j * 16;
        } else {
            src = (k16 < HD) ? (wih + row * HD + k16) : (whh + row * HD + (k16 - HD));
            dst = g_W + j * 16;
        }
        float4 v0 = *(const float4*)(src);
        float4 v1 = *(const float4*)(src + 4);
        float4 v2 = *(const float4*)(src + 8);
        float4 v3 = *(const float4*)(src + 12);
        __half2 h_[8];
        h_[0] = __floats2half2_rn(v0.x, v0.y); h_[1] = __floats2half2_rn(v0.z, v0.w);
        h_[2] = __floats2half2_rn(v1.x, v1.y); h_[3] = __floats2half2_rn(v1.z, v1.w);
        h_[4] = __floats2half2_rn(v2.x, v2.y); h_[5] = __floats2half2_rn(v2.z, v2.w);
        h_[6] = __floats2half2_rn(v3.x, v3.y); h_[7] = __floats2half2_rn(v3.z, v3.w);
        *(uint4*)(dst)     = *(uint4*)&h_[0];
        *(uint4*)(dst + 8) = *(uint4*)&h_[4];
    } else {
        const size_t p = id - 2 * NA16;          // 0 .. 6143
        if (p < NG) {
            g_BS[p] = b_ih[p] + b_hh[p];
        } else if (p < NG + HD) {
            const size_t h = p - NG;
            g_PI[h] = wpi[h * (HD + 1)];
        } else if (p < NG + 2 * HD) {
            const size_t h = p - NG - HD;
            g_PF[h] = wpf[h * (HD + 1)];
        }
    }
}

// ----------------------------- GEMM (champion, unchanged) ------------------
__global__ __launch_bounds__(256, 2)
void gates_gemm_f16() {
    extern __shared__ char smem[];
    const uint32_t sb = smem_u32(smem);

    const int tid  = threadIdx.x;
    const int lane = tid & 31;
    const int warp = tid >> 5;
    const int wm   = warp >> 2;          // 0..1 (64 rows each)
    const int wn   = warp & 3;           // 0..3 (32 cols each)
    const int bm   = blockIdx.y * BM;
    const int bn   = blockIdx.x * BN;

    const uint32_t aoff = (uint32_t)(lane & 15) * RSB + (uint32_t)(lane >> 4) * 16;
    const uint32_t boff = (uint32_t)(lane & 7) * RSB + (uint32_t)((lane >> 3) & 1) * 16
                        + (uint32_t)(lane >> 4) * (8 * RSB);

#define FILL(s_, kt_) do {                                                       \
        const uint32_t sa_ = sb + (uint32_t)(s_) * STG_BYTES;                    \
        const __half* ga_ = g_A + (size_t)(bm) * KT + (size_t)(kt_) * BKH;       \
        const __half* gw_ = g_W + (size_t)(bn) * KT + (size_t)(kt_) * BKH;       \
        _Pragma("unroll")                                                        \
        for (int i_ = 0; i_ < 4; i_++) {                                         \
            const int f_ = tid + i_ * 256;                                       \
            const int r_ = f_ >> 3, c_ = f_ & 7;                                 \
            cp16(sa_ + (uint32_t)r_ * RSB + (uint32_t)c_ * 16,                   \
                 ga_ + (size_t)r_ * KT + c_ * 8);                                \
            cp16(sa_ + TILE_BYTES + (uint32_t)r_ * RSB + (uint32_t)c_ * 16,      \
                 gw_ + (size_t)r_ * KT + c_ * 8);                                \
        }                                                                        \
    } while (0)

    FILL(0, 0); CP_COMMIT();
    FILL(1, 1); CP_COMMIT();

    float acc[4][4][4];
    #pragma unroll
    for (int i = 0; i < 4; i++)
        #pragma unroll
        for (int j = 0; j < 4; j++)
            #pragma unroll
            for (int e = 0; e < 4; e++) acc[i][j][e] = 0.0f;

    #pragma unroll 1
    for (int kt = 0; kt < KT / BKH; kt++) {       // 32 stages
        const int s = kt % 3;
        CP_WAIT1();
        __syncthreads();
        if (kt + 2 < KT / BKH) FILL((kt + 2) % 3, kt + 2);
        CP_COMMIT();

        const uint32_t sa = sb + (uint32_t)s * STG_BYTES;
        const uint32_t sw = sa + TILE_BYTES;
        #pragma unroll
        for (int ks = 0; ks < 4; ks++) {          // 16 halves each
            uint32_t a[4][4], b[4][2];
            #pragma unroll
            for (int mt = 0; mt < 4; mt++) {
                const uint32_t ad = sa + (uint32_t)(wm * 64 + mt * 16) * RSB
                                       + (uint32_t)ks * 32 + aoff;
                LDSM_X4(a[mt][0], a[mt][1], a[mt][2], a[mt][3], ad);
            }
            #pragma unroll
            for (int np = 0; np < 2; np++) {      // nt pairs {0,1},{2,3}
                const uint32_t bd = sw + (uint32_t)(wn * 32 + np * 16) * RSB
                                       + (uint32_t)ks * 32 + boff;
                LDSM_X4(b[np * 2][0], b[np * 2][1],
                        b[np * 2 + 1][0], b[np * 2 + 1][1], bd);
            }
            #pragma unroll
            for (int mt = 0; mt < 4; mt++)
                #pragma unroll
                for (int nt = 0; nt < 4; nt++)
                    MMA16816(acc[mt][nt], a[mt], b[nt]);
        }
    }
#undef FILL

    // store acc -> g_gates (fp16)
    const int g  = lane >> 2;
    const int tc = lane & 3;
    #pragma unroll
    for (int mt = 0; mt < 4; mt++) {
        #pragma unroll
        for (int nt = 0; nt < 4; nt++) {
            const int row = bm + wm * 64 + mt * 16 + g;
            const int col = bn + wn * 32 + nt * 8 + tc * 2;
            __half2* p0 = (__half2*)(g_gates + (size_t)row * NG + col);
            *p0 = __floats2half2_rn(acc[mt][nt][0], acc[mt][nt][1]);
            __half2* p1 = (__half2*)(g_gates + (size_t)(row + 8) * NG + col);
            *p1 = __floats2half2_rn(acc[mt][nt][2], acc[mt][nt][3]);
        }
    }
}

// ------------------- LSTM epilogue (2 batch rows per thread) ---------------
__global__ __launch_bounds__(256)
void lstm_epilogue(const float* __restrict__ cx, float* __restrict__ out) {
    // thread covers (b, h..h+3) and (b + MB/2, h..h+3): same h-constants.
    const int idx4 = (blockIdx.x * 256 + threadIdx.x) * 4;  // over MB/2 x HD
    const int b = idx4 >> 10;
    const int h = idx4 & (HD - 1);

    // h-constants loaded once, reused for both rows
    const float4 bs0 = *(const float4*)(g_BS + h);
    const float4 bs1 = *(const float4*)(g_BS + HD + h);
    const float4 bs2 = *(const float4*)(g_BS + 2 * HD + h);
    const float4 bs3 = *(const float4*)(g_BS + 3 * HD + h);
    const float4 pi4 = *(const float4*)(g_PI + h);
    const float4 pf4 = *(const float4*)(g_PF + h);
    const float bsi[4] = {bs0.x, bs0.y, bs0.z, bs0.w};
    const float bsf[4] = {bs1.x, bs1.y, bs1.z, bs1.w};
    const float bsg[4] = {bs2.x, bs2.y, bs2.z, bs2.w};
    const float bso[4] = {bs3.x, bs3.y, bs3.z, bs3.w};
    const float piv[4] = {pi4.x, pi4.y, pi4.z, pi4.w};
    const float pfv[4] = {pf4.x, pf4.y, pf4.z, pf4.w};

    #pragma unroll
    for (int rr = 0; rr < 2; rr++) {
        const int bb = b + rr * (MB / 2);
        const size_t base = (size_t)bb * HD + h;

        const __half* gr = g_gates + (size_t)bb * NG;
        float ig[4], fg[4], gg[4], og[4];
        #pragma unroll
        for (int G = 0; G < 4; G++) {
            const uint2 raw = *(const uint2*)(gr + G * HD + h);
            const float2 lo = __half22float2(*(const __half2*)&raw.x);
            const float2 hi = __half22float2(*(const __half2*)&raw.y);
            float* dst = (G == 0) ? ig : (G == 1) ? fg : (G == 2) ? gg : og;
            dst[0] = lo.x; dst[1] = lo.y; dst[2] = hi.x; dst[3] = hi.y;
        }
        const float4 c4 = *(const float4*)(cx + base);
        const float cv[4] = {c4.x, c4.y, c4.z, c4.w};

        float hy[4], cy[4];
        #pragma unroll
        for (int e = 0; e < 4; e++) {
            const float c  = cv[e];
            const float i_s = sigmoidf_(ig[e] + bsi[e] + c * piv[e]);
            const float f_s = sigmoidf_(fg[e] + bsf[e] + c * pfv[e]);
            const float g_t = tanhf(gg[e] + bsg[e]);
            const float cyv = f_s * c + i_s * g_t;
            const float o_s = sigmoidf_(og[e] + bso[e] + cyv * pfv[e]); // ref reuses W_f
            hy[e] = o_s * tanhf(cyv);
            cy[e] = cyv;
        }
        *(float4*)(out + base) = make_float4(hy[0], hy[1], hy[2], hy[3]);
        *(float4*)(out + (size_t)MB * HD + base) =
            make_float4(cy[0], cy[1], cy[2], cy[3]);
    }
}

// ---------------------------------------------------------------------------
extern "C" void kernel_launch(void* const* d_in, const int* in_sizes, int n_in,
                              void* d_out, int out_size) {
    const float* x    = (const float*)d_in[0];
    const float* hx   = (const float*)d_in[1];
    const float* cx   = (const float*)d_in[2];
    const float* w_ih = (const float*)d_in[3];
    const float* w_hh = (const float*)d_in[4];
    const float* b_ih = (const float*)d_in[5];
    const float* b_hh = (const float*)d_in[6];
    const float* wpi  = (const float*)d_in[7];
    const float* wpf  = (const float*)d_in[8];
    // d_in[9] (W_peephole_o) unused: reference reuses W_peephole_f.
    float* out = (float*)d_out;

    // 4096 data blocks + 24 prep blocks (6144 prep elements)
    convert_f16<<<4120, 256>>>(x, hx, w_ih, w_hh, b_ih, b_hh, wpi, wpf);

    static int smem_set = 0;
    if (!smem_set) {
        cudaFuncSetAttribute(gates_gemm_f16,
                             cudaFuncAttributeMaxDynamicSharedMemorySize,
                             SMEM_BYTES);
        smem_set = 1;
    }
    dim3 grid(NG / BN, MB / BM);   // 32 x 32
    gates_gemm_f16<<<grid, 256, SMEM_BYTES>>>();

    // (MB/2 * HD) / 4 elems per thread / 256 threads = 2048 blocks
    lstm_epilogue<<<(MB / 2 * HD) / 1024, 256>>>(cx, out);
}